// round 13
// baseline (speedup 1.0000x reference)
#include <cuda_runtime.h>
#include <cstdint>

#define KA     36864
#define NIMG   8
#define NPRE   3000
#define NPOST  300

// d_out layout (float32, concatenated in reference return order)
#define OFF_LOCS    0
#define OFF_SCORES  1179648
#define OFF_ROIS    1769472
#define OFF_RIDX    1779072
#define OFF_ANCHOR  1781472

// ---------------- device scratch ----------------
__device__ float g_Wt [4608 * 512];                  // 3x3 weights [k][o], k=kpos*512+c
__device__ float g_h  [(size_t)NIMG * 4096 * 512];   // conv output NHWC fp32
__device__ float g_Wt2[512 * 64];
__device__ float g_roi[(size_t)NIMG * KA * 4];
__device__ float g_sc [(size_t)NIMG * KA];

__constant__ float c_base[9][4] = {
  {-90.50966799187809f,  -45.254833995939045f,  90.50966799187809f,  45.254833995939045f},
  {-181.01933598375618f, -90.50966799187809f,  181.01933598375618f,  90.50966799187809f},
  {-362.03867196751236f, -181.01933598375618f, 362.03867196751236f, 181.01933598375618f},
  {-64.f, -64.f, 64.f, 64.f},
  {-128.f,-128.f,128.f,128.f},
  {-256.f,-256.f,256.f,256.f},
  {-45.254833995939045f, -90.50966799187809f,   45.254833995939045f, 90.50966799187809f},
  {-90.50966799187809f,  -181.01933598375618f,  90.50966799187809f, 181.01933598375618f},
  {-181.01933598375618f, -362.03867196751236f, 181.01933598375618f, 362.03867196751236f},
};

// ---------------- weight prep + anchors (merged, one launch) ----------------
#define PW_W1   (4608 * 512)
#define PW_W2   (512 * 64)
__global__ void prep_w(const float* __restrict__ W1,
                       const float* __restrict__ Wl, const float* __restrict__ Ws,
                       float* __restrict__ out) {
  int idx = blockIdx.x * 256 + threadIdx.x;
  if (idx < PW_W1) {
    int o = idx & 511;
    int kc = idx >> 9;       // kpos*512 + c
    int c = kc & 511;
    int kpos = kc >> 9;
    g_Wt[idx] = W1[(((o << 9) | c) * 9) + kpos];
  } else if (idx < PW_W1 + PW_W2) {
    int i2 = idx - PW_W1;
    int o = i2 & 63;
    int c = i2 >> 6;
    float v = 0.f;
    if (o < 36)      v = Wl[o * 512 + c];
    else if (o < 54) v = Ws[(o - 36) * 512 + c];
    g_Wt2[i2] = v;
  } else {
    int j = idx - PW_W1 - PW_W2;
    if (j < KA) {
      int pix = j / 9;
      int a = j - pix * 9;
      int yy = pix >> 6, xx = pix & 63;
      float sx = xx * 16.f, sy = yy * 16.f;
      out[OFF_ANCHOR + j * 4 + 0] = sx + c_base[a][0];
      out[OFF_ANCHOR + j * 4 + 1] = sy + c_base[a][1];
      out[OFF_ANCHOR + j * 4 + 2] = sx + c_base[a][2];
      out[OFF_ANCHOR + j * 4 + 3] = sy + c_base[a][3];
    }
  }
}

// ---------------- 3x3 conv + bias + relu (exact fp32, bit-identical chain to R1) ----------
// FROZEN (R10 exact): CTA 128 pixels x 128 ochans, 256 threads, thread tile 8x8.
// K = 9*512 in chunks of 16, kpos-major.  Double-buffered smem, one sync per chunk.
__global__ void __launch_bounds__(256, 2) conv3x3(const float* __restrict__ x,
                                                  const float* __restrict__ b1) {
  __shared__ float As[2][16][128];
  __shared__ float Bs[2][16][128];

  int t  = threadIdx.x;
  int pix0 = blockIdx.x * 128;
  int o0 = blockIdx.y * 128;
  int n  = pix0 >> 12;
  int y0 = (pix0 >> 6) & 63;
  int ty = t >> 4, tx = t & 15;
  int cc0 = t >> 7;        // 0..1  (k-row pair selector)
  int pl  = t & 127;       // column (pixel / ochan)

  float ra[8], rb[8];

  // ---- prefetch chunk 0 (kpos=0, c0=0) ----
  {
    int yy = y0 + (pl >> 6) - 1;
    int xx = (pl & 63) - 1;
    bool ok = ((unsigned)yy < 64u) && ((unsigned)xx < 64u);
#pragma unroll
    for (int i = 0; i < 8; i++) {
      int cch = i * 2 + cc0;
      ra[i] = ok ? x[(((size_t)(n * 512 + cch)) << 12) + yy * 64 + xx] : 0.f;
      rb[i] = g_Wt[((size_t)cch << 9) + o0 + pl];
    }
  }

  float acc[8][8];
#pragma unroll
  for (int i = 0; i < 8; i++)
#pragma unroll
    for (int j = 0; j < 8; j++) acc[i][j] = 0.f;

  for (int c = 0; c < 288; c++) {
    int buf = c & 1;
    // ---- store prefetched regs to smem ----
#pragma unroll
    for (int i = 0; i < 8; i++) {
      As[buf][i * 2 + cc0][pl] = ra[i];
      Bs[buf][i * 2 + cc0][pl] = rb[i];
    }
    __syncthreads();

    // ---- prefetch next chunk ----
    if (c + 1 < 288) {
      int c2 = c + 1;
      int kpos = c2 >> 5, c0 = (c2 & 31) << 4;
      int dy = kpos / 3 - 1, dx = kpos % 3 - 1;
      int yy = y0 + (pl >> 6) + dy;
      int xx = (pl & 63) + dx;
      bool ok = ((unsigned)yy < 64u) && ((unsigned)xx < 64u);
#pragma unroll
      for (int i = 0; i < 8; i++) {
        int cch = c0 + i * 2 + cc0;
        ra[i] = ok ? x[(((size_t)(n * 512 + cch)) << 12) + yy * 64 + xx] : 0.f;
        rb[i] = g_Wt[((size_t)(kpos * 512 + cch) << 9) + o0 + pl];
      }
    }

    // ---- compute (k order identical to R1: kk 0..15 ascending) ----
#pragma unroll
    for (int kk = 0; kk < 16; kk++) {
      float4 a0  = *(const float4*)&As[buf][kk][ty * 8];
      float4 a1  = *(const float4*)&As[buf][kk][ty * 8 + 4];
      float4 b0  = *(const float4*)&Bs[buf][kk][tx * 8];
      float4 b1v = *(const float4*)&Bs[buf][kk][tx * 8 + 4];
      float a[8] = {a0.x, a0.y, a0.z, a0.w, a1.x, a1.y, a1.z, a1.w};
      float b[8] = {b0.x, b0.y, b0.z, b0.w, b1v.x, b1v.y, b1v.z, b1v.w};
#pragma unroll
      for (int i = 0; i < 8; i++)
#pragma unroll
        for (int j = 0; j < 8; j++) acc[i][j] = fmaf(a[i], b[j], acc[i][j]);
    }
  }

  // ---- epilogue: bias + relu, write NHWC (identical op order to R1) ----
#pragma unroll
  for (int i = 0; i < 8; i++) {
    int p = pix0 + ty * 8 + i;
#pragma unroll
    for (int j = 0; j < 8; j++) {
      int o = o0 + tx * 8 + j;
      float v = acc[i][j] + b1[o];
      g_h[(size_t)p * 512 + o] = fmaxf(v, 0.f);
    }
  }
}

// ---------------- helpers ----------------
__device__ __forceinline__ float scalar_val(const int* p) {
  if (!p) return 1024.f;
  int iv = *p;
  if (iv > 0 && iv < (1 << 20)) return (float)iv;
  return __int_as_float(iv);
}

// ---------------- 1x1 heads + fused roi decode ----------------
__global__ void __launch_bounds__(256) conv1x1(const float* __restrict__ bl,
                                               const float* __restrict__ bs,
                                               const int* __restrict__ ihp,
                                               const int* __restrict__ iwp,
                                               float* __restrict__ out) {
  __shared__ __align__(16) float As2[16][68];
  __shared__ __align__(16) float Bs2c[16][64];
  __shared__ float Vals[64][56];   // [local pixel][output 0..53]

  int t  = threadIdx.x;
  int p0 = blockIdx.x * 64;
  int ty = t >> 4, tx = t & 15;

  float acc[4][4];
#pragma unroll
  for (int i = 0; i < 4; i++)
#pragma unroll
    for (int j = 0; j < 4; j++) acc[i][j] = 0.f;

  for (int c0 = 0; c0 < 512; c0 += 16) {
#pragma unroll
    for (int i = 0; i < 4; i++) {
      int l  = i * 256 + t;
      int pl = l >> 4;
      int kk = l & 15;
      As2[kk][pl] = g_h[(size_t)(p0 + pl) * 512 + c0 + kk];
    }
#pragma unroll
    for (int i = 0; i < 4; i++) {
      int l  = i * 256 + t;
      int kk = l >> 6;
      int oo = l & 63;
      Bs2c[kk][oo] = g_Wt2[(c0 + kk) * 64 + oo];
    }
    __syncthreads();
#pragma unroll
    for (int kk = 0; kk < 16; kk++) {
      float4 av = *(const float4*)&As2[kk][ty * 4];
      float4 bv = *(const float4*)&Bs2c[kk][tx * 4];
      float a[4] = {av.x, av.y, av.z, av.w};
      float b[4] = {bv.x, bv.y, bv.z, bv.w};
#pragma unroll
      for (int i = 0; i < 4; i++)
#pragma unroll
        for (int j = 0; j < 4; j++) acc[i][j] = fmaf(a[i], b[j], acc[i][j]);
    }
    __syncthreads();
  }

  // write head outputs; stage values for in-block decode
#pragma unroll
  for (int i = 0; i < 4; i++) {
    int pli = ty * 4 + i;
    int p = p0 + pli;
#pragma unroll
    for (int j = 0; j < 4; j++) {
      int o = tx * 4 + j;
      if (o < 36) {
        float v = acc[i][j] + bl[o];
        out[OFF_LOCS + (size_t)p * 36 + o] = v;
        Vals[pli][o] = v;
      } else if (o < 54) {
        float v = acc[i][j] + bs[o - 36];
        out[OFF_SCORES + (size_t)p * 18 + (o - 36)] = v;
        Vals[pli][o] = v;
      }
    }
  }
  __syncthreads();

  // decode 576 anchors of this block (same formulas as before)
  float imh = scalar_val(ihp);
  float imw = scalar_val(iwp);
  for (int idx = t; idx < 64 * 9; idx += 256) {
    int pli = idx / 9;
    int a = idx - pli * 9;
    int p = p0 + pli;
    int n = p >> 12;
    int pix = p & 4095;
    int yy = pix >> 6, xx = pix & 63;
    float sx = xx * 16.f, sy = yy * 16.f;
    float ax1 = sx + c_base[a][0];
    float ay1 = sy + c_base[a][1];
    float ax2 = sx + c_base[a][2];
    float ay2 = sy + c_base[a][3];

    float lx = Vals[pli][a * 4 + 0];
    float ly = Vals[pli][a * 4 + 1];
    float lz = Vals[pli][a * 4 + 2];
    float lw = Vals[pli][a * 4 + 3];
    float s0 = Vals[pli][36 + a * 2];
    float s1 = Vals[pli][36 + a * 2 + 1];
    float fg = 1.f / (1.f + expf(s0 - s1));

    float w  = ax2 - ax1, h = ay2 - ay1;
    float cx = ax1 + 0.5f * w, cy = ay1 + 0.5f * h;
    float ncx = lx * w + cx;
    float ncy = ly * h + cy;
    float nw  = expf(lz) * w;
    float nh  = expf(lw) * h;
    float x1 = fminf(fmaxf(ncx - 0.5f * nw, 0.f), imw);
    float y1 = fminf(fmaxf(ncy - 0.5f * nh, 0.f), imh);
    float x2 = fminf(fmaxf(ncx + 0.5f * nw, 0.f), imw);
    float y2 = fminf(fmaxf(ncy + 0.5f * nh, 0.f), imh);
    float ws = x2 - x1, hs = y2 - y1;
    float sc = (ws >= 16.f && hs >= 16.f) ? fg : -1e9f;

    size_t gidx = (size_t)n * KA + (size_t)pix * 9 + a;
    *(float4*)(g_roi + gidx * 4) = make_float4(x1, y1, x2, y2);
    g_sc[gidx] = sc;
  }
}

// ---------------- exact top-3000 + greedy NMS, one block per image ----------------
// v3: ONE barrier per greedy iteration — per-warp maxima in a double-buffered
// red[2][32]; every warp redundantly reduces and broadcasts lane 0.
__device__ __forceinline__ unsigned f2mono(float f) {
  unsigned u = __float_as_uint(f);
  return (u & 0x80000000u) ? ~u : (u | 0x80000000u);
}
__device__ __forceinline__ unsigned long long make_key(float s, int j) {
  return (((unsigned long long)(~f2mono(s))) << 32) | (unsigned)j;
}

#define NMS_SMEM (4096 * 8 + 5 * NPRE * 4)

extern __shared__ __align__(1024) unsigned char nms_dsm[];

__global__ void __launch_bounds__(1024, 1) nms_kernel(float* __restrict__ out) {
  unsigned long long* keys = (unsigned long long*)nms_dsm;
  float* bx1 = (float*)(nms_dsm + 4096 * 8);
  float* by1 = bx1 + NPRE;
  float* bx2 = by1 + NPRE;
  float* by2 = bx2 + NPRE;
  float* ar  = by2 + NPRE;
  __shared__ unsigned hist[256];
  __shared__ unsigned long long red[2][32];
  __shared__ int keep_s[NPOST];
  __shared__ unsigned long long sPrefix;
  __shared__ int sR, sCnt;

  int n = blockIdx.x;
  int t = threadIdx.x;
  const float* sc = g_sc + (size_t)n * KA;

  if (t == 0) { sPrefix = 0ull; sR = NPRE - 1; sCnt = 0; }
  __syncthreads();

  for (int d = 7; d >= 0; d--) {
    if (t < 256) hist[t] = 0;
    __syncthreads();
    unsigned long long pref = sPrefix;
    int shift = d * 8;
    for (int j = t; j < KA; j += 1024) {
      unsigned long long key = make_key(sc[j], j);
      bool inpref = (d == 7) || (((key ^ pref) >> (shift + 8)) == 0ull);
      if (inpref) atomicAdd(&hist[(unsigned)((key >> shift) & 255ull)], 1u);
    }
    __syncthreads();
    if (t == 0) {
      int r = sR, cum = 0, b = 0;
      for (; b < 255; b++) {
        int hb = (int)hist[b];
        if (cum + hb > r) break;
        cum += hb;
      }
      sR = r - cum;
      sPrefix = pref | ((unsigned long long)b << shift);
    }
    __syncthreads();
  }
  unsigned long long T = sPrefix;

  for (int i = t; i < 4096; i += 1024) keys[i] = ~0ull;
  __syncthreads();
  for (int j = t; j < KA; j += 1024) {
    unsigned long long key = make_key(sc[j], j);
    if (key <= T) { int pos = atomicAdd(&sCnt, 1); if (pos < 4096) keys[pos] = key; }
  }
  __syncthreads();

  for (int k = 2; k <= 4096; k <<= 1) {
    for (int s = k >> 1; s > 0; s >>= 1) {
      for (int i = t; i < 4096; i += 1024) {
        int l = i ^ s;
        if (l > i) {
          unsigned long long A = keys[i], B = keys[l];
          bool asc = ((i & k) == 0);
          if ((A > B) == asc) { keys[i] = B; keys[l] = A; }
        }
      }
      __syncthreads();
    }
  }

  float rbx1[3], rby1[3], rbx2[3], rby2[3], rar[3], rss[3];
#pragma unroll
  for (int k = 0; k < 3; k++) {
    int i = t + k * 1024;
    if (i < NPRE) {
      int j = (int)(keys[i] & 0xffffffffull);
      float4 bb = *(const float4*)(g_roi + ((size_t)n * KA + j) * 4);
      float area = (bb.z - bb.x) * (bb.w - bb.y);
      bx1[i] = bb.x; by1[i] = bb.y; bx2[i] = bb.z; by2[i] = bb.w; ar[i] = area;
      rbx1[k] = bb.x; rby1[k] = bb.y; rbx2[k] = bb.z; rby2[k] = bb.w;
      rar[k] = area; rss[k] = sc[j];
    }
  }

  int lane = t & 31, warp = t >> 5;
  const unsigned monoThr = f2mono(-5e8f);
  unsigned long long cur;

  // initial argmax (buffer parity 1; iteration 0 uses parity 0)
  {
    unsigned long long best = 0ull;
#pragma unroll
    for (int k = 0; k < 3; k++) {
      int i = t + k * 1024;
      if (i < NPRE) {
        unsigned long long cand =
            (((unsigned long long)f2mono(rss[k])) << 32) | (unsigned)(~(unsigned)i);
        if (cand > best) best = cand;
      }
    }
#pragma unroll
    for (int off = 16; off > 0; off >>= 1) {
      unsigned long long o2 = __shfl_down_sync(0xffffffffu, best, off);
      if (o2 > best) best = o2;
    }
    if (lane == 0) red[1][warp] = best;
    __syncthreads();
    unsigned long long v = red[1][lane];
#pragma unroll
    for (int off = 16; off > 0; off >>= 1) {
      unsigned long long o2 = __shfl_down_sync(0xffffffffu, v, off);
      if (o2 > v) v = o2;
    }
    cur = __shfl_sync(0xffffffffu, v, 0);
  }

  // fused greedy loop: ONE barrier per iteration
  for (int it = 0; it < NPOST; it++) {
    int ij = (int)(~(unsigned)(cur & 0xffffffffull));
    bool valid = ((unsigned)(cur >> 32)) > monoThr;
    if (t == 0) keep_s[it] = valid ? ij : -1;
    float jx1 = bx1[ij], jy1 = by1[ij], jx2 = bx2[ij], jy2 = by2[ij], ja = ar[ij];

    unsigned long long best = 0ull;
#pragma unroll
    for (int k = 0; k < 3; k++) {
      int i = t + k * 1024;
      if (i < NPRE) {
        float xx1 = fmaxf(rbx1[k], jx1);
        float yy1 = fmaxf(rby1[k], jy1);
        float xx2 = fminf(rbx2[k], jx2);
        float yy2 = fminf(rby2[k], jy2);
        float inter = fmaxf(xx2 - xx1, 0.f) * fmaxf(yy2 - yy1, 0.f);
        float iou = inter / (rar[k] + ja - inter + 1e-9f);
        if (iou > 0.7f || i == ij || !valid) rss[k] = -1e9f;
        unsigned long long cand =
            (((unsigned long long)f2mono(rss[k])) << 32) | (unsigned)(~(unsigned)i);
        if (cand > best) best = cand;
      }
    }
#pragma unroll
    for (int off = 16; off > 0; off >>= 1) {
      unsigned long long o2 = __shfl_down_sync(0xffffffffu, best, off);
      if (o2 > best) best = o2;
    }
    int buf = it & 1;
    if (lane == 0) red[buf][warp] = best;
    __syncthreads();                      // also protects red[buf^1] reuse next it
    unsigned long long v = red[buf][lane];
#pragma unroll
    for (int off = 16; off > 0; off >>= 1) {
      unsigned long long o2 = __shfl_down_sync(0xffffffffu, v, off);
      if (o2 > v) v = o2;
    }
    cur = __shfl_sync(0xffffffffu, v, 0);
  }
  __syncthreads();

  for (int i = t; i < NPOST; i += 1024) {
    int kk = keep_s[i];
    float ox1 = 0.f, oy1 = 0.f, ox2 = 0.f, oy2 = 0.f, ridx = -1.f;
    if (kk >= 0) { ox1 = bx1[kk]; oy1 = by1[kk]; ox2 = bx2[kk]; oy2 = by2[kk]; ridx = (float)n; }
    int o = n * NPOST + i;
    out[OFF_ROIS + o * 4 + 0] = ox1;
    out[OFF_ROIS + o * 4 + 1] = oy1;
    out[OFF_ROIS + o * 4 + 2] = ox2;
    out[OFF_ROIS + o * 4 + 3] = oy2;
    out[OFF_RIDX + o] = ridx;
  }
}

// ---------------- launch ----------------
extern "C" void kernel_launch(void* const* d_in, const int* in_sizes, int n_in,
                              void* d_out, int out_size) {
  const float* x  = (const float*)d_in[0];
  const float* W1 = (const float*)d_in[1];
  const float* b1 = (const float*)d_in[2];
  const float* Ws = (const float*)d_in[3];
  const float* bs = (const float*)d_in[4];
  const float* Wl = (const float*)d_in[5];
  const float* bl = (const float*)d_in[6];
  const int* ih = (n_in > 7) ? (const int*)d_in[7] : nullptr;
  const int* iw = (n_in > 8) ? (const int*)d_in[8] : nullptr;
  float* out = (float*)d_out;

  cudaFuncSetAttribute(nms_kernel, cudaFuncAttributeMaxDynamicSharedMemorySize, NMS_SMEM);

  prep_w<<<(PW_W1 + PW_W2 + KA + 255) / 256, 256>>>(W1, Wl, Ws, out);
  conv3x3<<<dim3(256, 4), 256>>>(x, b1);
  conv1x1<<<512, 256>>>(bl, bs, ih, iw, out);
  nms_kernel<<<NIMG, 1024, NMS_SMEM>>>(out);
}

// round 14
// speedup vs baseline: 1.6030x; 1.6030x over previous
#include <cuda_runtime.h>
#include <cstdint>

#define KA     36864
#define NIMG   8
#define NPRE   3000
#define NPOST  300

// d_out layout (float32, concatenated in reference return order)
#define OFF_LOCS    0
#define OFF_SCORES  1179648
#define OFF_ROIS    1769472
#define OFF_RIDX    1779072
#define OFF_ANCHOR  1781472

// ---------------- device scratch ----------------
__device__ float g_Wt [4608 * 512];                  // 3x3 weights [k][o], k=kpos*512+c
__device__ float g_h  [(size_t)NIMG * 4096 * 512];   // conv output NHWC fp32
__device__ float g_Wt2[512 * 64];
__device__ float g_roi[(size_t)NIMG * KA * 4];
__device__ float g_sc [(size_t)NIMG * KA];

__constant__ float c_base[9][4] = {
  {-90.50966799187809f,  -45.254833995939045f,  90.50966799187809f,  45.254833995939045f},
  {-181.01933598375618f, -90.50966799187809f,  181.01933598375618f,  90.50966799187809f},
  {-362.03867196751236f, -181.01933598375618f, 362.03867196751236f, 181.01933598375618f},
  {-64.f, -64.f, 64.f, 64.f},
  {-128.f,-128.f,128.f,128.f},
  {-256.f,-256.f,256.f,256.f},
  {-45.254833995939045f, -90.50966799187809f,   45.254833995939045f, 90.50966799187809f},
  {-90.50966799187809f,  -181.01933598375618f,  90.50966799187809f, 181.01933598375618f},
  {-181.01933598375618f, -362.03867196751236f, 181.01933598375618f, 362.03867196751236f},
};

// ---------------- weight prep + anchors (one launch) ----------------
// Blocks [0,256): smem-tiled transpose of W1 (coalesced reads, 128B writes).
// Blocks [256,...): 1x1-head weights + anchor table.
__global__ void prep_w(const float* __restrict__ W1,
                       const float* __restrict__ Wl, const float* __restrict__ Ws,
                       float* __restrict__ out) {
  if (blockIdx.x < 256) {
    __shared__ float sm[32][289];        // stride 289 == 1 mod 32: conflict-free cols
    int bx = blockIdx.x & 15;            // o tile
    int by = blockIdx.x >> 4;            // c tile
    int o0 = bx * 32, c0 = by * 32;
    int t = threadIdx.x;
    // load: 32 o-rows x 288 contiguous floats (c*9+kpos), fully coalesced
#pragma unroll
    for (int i = 0; i < 36; i++) {
      int l = i * 256 + t;
      int oi = l / 288;
      int r  = l - oi * 288;
      sm[oi][r] = W1[(size_t)(o0 + oi) * 4608 + c0 * 9 + r];
    }
    __syncthreads();
    // write: row = c*9+kpos -> g_Wt[(kpos*512 + c0+c)*512 + o0 + lane]
#pragma unroll
    for (int j = 0; j < 36; j++) {
      int l = j * 256 + t;
      int row = l >> 5;                  // 0..287
      int lo  = l & 31;                  // o lane
      int cc = row / 9;
      int kpos = row - cc * 9;
      g_Wt[(size_t)(kpos * 512 + c0 + cc) * 512 + o0 + lo] = sm[lo][row];
    }
  } else {
    int idx = (blockIdx.x - 256) * 256 + threadIdx.x;
    if (idx < 512 * 64) {
      int o = idx & 63;
      int c = idx >> 6;
      float v = 0.f;
      if (o < 36)      v = Wl[o * 512 + c];
      else if (o < 54) v = Ws[(o - 36) * 512 + c];
      g_Wt2[idx] = v;
    } else {
      int j = idx - 512 * 64;
      if (j < KA) {
        int pix = j / 9;
        int a = j - pix * 9;
        int yy = pix >> 6, xx = pix & 63;
        float sx = xx * 16.f, sy = yy * 16.f;
        out[OFF_ANCHOR + j * 4 + 0] = sx + c_base[a][0];
        out[OFF_ANCHOR + j * 4 + 1] = sy + c_base[a][1];
        out[OFF_ANCHOR + j * 4 + 2] = sx + c_base[a][2];
        out[OFF_ANCHOR + j * 4 + 3] = sy + c_base[a][3];
      }
    }
  }
}

// ---------------- 3x3 conv + bias + relu (exact fp32, bit-identical chain to R1) ----------
// FROZEN (R10 exact): CTA 128 pixels x 128 ochans, 256 threads, thread tile 8x8.
// K = 9*512 in chunks of 16, kpos-major.  Double-buffered smem, one sync per chunk.
__global__ void __launch_bounds__(256, 2) conv3x3(const float* __restrict__ x,
                                                  const float* __restrict__ b1) {
  __shared__ float As[2][16][128];
  __shared__ float Bs[2][16][128];

  int t  = threadIdx.x;
  int pix0 = blockIdx.x * 128;
  int o0 = blockIdx.y * 128;
  int n  = pix0 >> 12;
  int y0 = (pix0 >> 6) & 63;
  int ty = t >> 4, tx = t & 15;
  int cc0 = t >> 7;        // 0..1  (k-row pair selector)
  int pl  = t & 127;       // column (pixel / ochan)

  float ra[8], rb[8];

  // ---- prefetch chunk 0 (kpos=0, c0=0) ----
  {
    int yy = y0 + (pl >> 6) - 1;
    int xx = (pl & 63) - 1;
    bool ok = ((unsigned)yy < 64u) && ((unsigned)xx < 64u);
#pragma unroll
    for (int i = 0; i < 8; i++) {
      int cch = i * 2 + cc0;
      ra[i] = ok ? x[(((size_t)(n * 512 + cch)) << 12) + yy * 64 + xx] : 0.f;
      rb[i] = g_Wt[((size_t)cch << 9) + o0 + pl];
    }
  }

  float acc[8][8];
#pragma unroll
  for (int i = 0; i < 8; i++)
#pragma unroll
    for (int j = 0; j < 8; j++) acc[i][j] = 0.f;

  for (int c = 0; c < 288; c++) {
    int buf = c & 1;
#pragma unroll
    for (int i = 0; i < 8; i++) {
      As[buf][i * 2 + cc0][pl] = ra[i];
      Bs[buf][i * 2 + cc0][pl] = rb[i];
    }
    __syncthreads();

    if (c + 1 < 288) {
      int c2 = c + 1;
      int kpos = c2 >> 5, c0 = (c2 & 31) << 4;
      int dy = kpos / 3 - 1, dx = kpos % 3 - 1;
      int yy = y0 + (pl >> 6) + dy;
      int xx = (pl & 63) + dx;
      bool ok = ((unsigned)yy < 64u) && ((unsigned)xx < 64u);
#pragma unroll
      for (int i = 0; i < 8; i++) {
        int cch = c0 + i * 2 + cc0;
        ra[i] = ok ? x[(((size_t)(n * 512 + cch)) << 12) + yy * 64 + xx] : 0.f;
        rb[i] = g_Wt[((size_t)(kpos * 512 + cch) << 9) + o0 + pl];
      }
    }

#pragma unroll
    for (int kk = 0; kk < 16; kk++) {
      float4 a0  = *(const float4*)&As[buf][kk][ty * 8];
      float4 a1  = *(const float4*)&As[buf][kk][ty * 8 + 4];
      float4 b0  = *(const float4*)&Bs[buf][kk][tx * 8];
      float4 b1v = *(const float4*)&Bs[buf][kk][tx * 8 + 4];
      float a[8] = {a0.x, a0.y, a0.z, a0.w, a1.x, a1.y, a1.z, a1.w};
      float b[8] = {b0.x, b0.y, b0.z, b0.w, b1v.x, b1v.y, b1v.z, b1v.w};
#pragma unroll
      for (int i = 0; i < 8; i++)
#pragma unroll
        for (int j = 0; j < 8; j++) acc[i][j] = fmaf(a[i], b[j], acc[i][j]);
    }
  }

#pragma unroll
  for (int i = 0; i < 8; i++) {
    int p = pix0 + ty * 8 + i;
#pragma unroll
    for (int j = 0; j < 8; j++) {
      int o = o0 + tx * 8 + j;
      float v = acc[i][j] + b1[o];
      g_h[(size_t)p * 512 + o] = fmaxf(v, 0.f);
    }
  }
}

// ---------------- helpers ----------------
__device__ __forceinline__ float scalar_val(const int* p) {
  if (!p) return 1024.f;
  int iv = *p;
  if (iv > 0 && iv < (1 << 20)) return (float)iv;
  return __int_as_float(iv);
}

// ---------------- 1x1 heads + fused roi decode ----------------
__global__ void __launch_bounds__(256) conv1x1(const float* __restrict__ bl,
                                               const float* __restrict__ bs,
                                               const int* __restrict__ ihp,
                                               const int* __restrict__ iwp,
                                               float* __restrict__ out) {
  __shared__ __align__(16) float As2[16][68];
  __shared__ __align__(16) float Bs2c[16][64];
  __shared__ float Vals[64][56];   // [local pixel][output 0..53]

  int t  = threadIdx.x;
  int p0 = blockIdx.x * 64;
  int ty = t >> 4, tx = t & 15;

  float acc[4][4];
#pragma unroll
  for (int i = 0; i < 4; i++)
#pragma unroll
    for (int j = 0; j < 4; j++) acc[i][j] = 0.f;

  for (int c0 = 0; c0 < 512; c0 += 16) {
#pragma unroll
    for (int i = 0; i < 4; i++) {
      int l  = i * 256 + t;
      int pl = l >> 4;
      int kk = l & 15;
      As2[kk][pl] = g_h[(size_t)(p0 + pl) * 512 + c0 + kk];
    }
#pragma unroll
    for (int i = 0; i < 4; i++) {
      int l  = i * 256 + t;
      int kk = l >> 6;
      int oo = l & 63;
      Bs2c[kk][oo] = g_Wt2[(c0 + kk) * 64 + oo];
    }
    __syncthreads();
#pragma unroll
    for (int kk = 0; kk < 16; kk++) {
      float4 av = *(const float4*)&As2[kk][ty * 4];
      float4 bv = *(const float4*)&Bs2c[kk][tx * 4];
      float a[4] = {av.x, av.y, av.z, av.w};
      float b[4] = {bv.x, bv.y, bv.z, bv.w};
#pragma unroll
      for (int i = 0; i < 4; i++)
#pragma unroll
        for (int j = 0; j < 4; j++) acc[i][j] = fmaf(a[i], b[j], acc[i][j]);
    }
    __syncthreads();
  }

#pragma unroll
  for (int i = 0; i < 4; i++) {
    int pli = ty * 4 + i;
    int p = p0 + pli;
#pragma unroll
    for (int j = 0; j < 4; j++) {
      int o = tx * 4 + j;
      if (o < 36) {
        float v = acc[i][j] + bl[o];
        out[OFF_LOCS + (size_t)p * 36 + o] = v;
        Vals[pli][o] = v;
      } else if (o < 54) {
        float v = acc[i][j] + bs[o - 36];
        out[OFF_SCORES + (size_t)p * 18 + (o - 36)] = v;
        Vals[pli][o] = v;
      }
    }
  }
  __syncthreads();

  float imh = scalar_val(ihp);
  float imw = scalar_val(iwp);
  for (int idx = t; idx < 64 * 9; idx += 256) {
    int pli = idx / 9;
    int a = idx - pli * 9;
    int p = p0 + pli;
    int n = p >> 12;
    int pix = p & 4095;
    int yy = pix >> 6, xx = pix & 63;
    float sx = xx * 16.f, sy = yy * 16.f;
    float ax1 = sx + c_base[a][0];
    float ay1 = sy + c_base[a][1];
    float ax2 = sx + c_base[a][2];
    float ay2 = sy + c_base[a][3];

    float lx = Vals[pli][a * 4 + 0];
    float ly = Vals[pli][a * 4 + 1];
    float lz = Vals[pli][a * 4 + 2];
    float lw = Vals[pli][a * 4 + 3];
    float s0 = Vals[pli][36 + a * 2];
    float s1 = Vals[pli][36 + a * 2 + 1];
    float fg = 1.f / (1.f + expf(s0 - s1));

    float w  = ax2 - ax1, h = ay2 - ay1;
    float cx = ax1 + 0.5f * w, cy = ay1 + 0.5f * h;
    float ncx = lx * w + cx;
    float ncy = ly * h + cy;
    float nw  = expf(lz) * w;
    float nh  = expf(lw) * h;
    float x1 = fminf(fmaxf(ncx - 0.5f * nw, 0.f), imw);
    float y1 = fminf(fmaxf(ncy - 0.5f * nh, 0.f), imh);
    float x2 = fminf(fmaxf(ncx + 0.5f * nw, 0.f), imw);
    float y2 = fminf(fmaxf(ncy + 0.5f * nh, 0.f), imh);
    float ws = x2 - x1, hs = y2 - y1;
    float sc = (ws >= 16.f && hs >= 16.f) ? fg : -1e9f;

    size_t gidx = (size_t)n * KA + (size_t)pix * 9 + a;
    *(float4*)(g_roi + gidx * 4) = make_float4(x1, y1, x2, y2);
    g_sc[gidx] = sc;
  }
}

// ---------------- exact top-3000 + greedy NMS, one block per image ----------------
// v2 (proven fastest): fused suppress+argmax, two barriers per iteration.
__device__ __forceinline__ unsigned f2mono(float f) {
  unsigned u = __float_as_uint(f);
  return (u & 0x80000000u) ? ~u : (u | 0x80000000u);
}
__device__ __forceinline__ unsigned long long make_key(float s, int j) {
  return (((unsigned long long)(~f2mono(s))) << 32) | (unsigned)j;
}

#define NMS_SMEM (4096 * 8 + 5 * NPRE * 4)

extern __shared__ __align__(1024) unsigned char nms_dsm[];

__global__ void __launch_bounds__(1024, 1) nms_kernel(float* __restrict__ out) {
  unsigned long long* keys = (unsigned long long*)nms_dsm;
  float* bx1 = (float*)(nms_dsm + 4096 * 8);
  float* by1 = bx1 + NPRE;
  float* bx2 = by1 + NPRE;
  float* by2 = bx2 + NPRE;
  float* ar  = by2 + NPRE;
  __shared__ unsigned hist[256];
  __shared__ unsigned long long red[32];
  __shared__ int keep_s[NPOST];
  __shared__ unsigned long long sPrefix, sBest;
  __shared__ int sR, sCnt;

  int n = blockIdx.x;
  int t = threadIdx.x;
  const float* sc = g_sc + (size_t)n * KA;

  if (t == 0) { sPrefix = 0ull; sR = NPRE - 1; sCnt = 0; }
  __syncthreads();

  for (int d = 7; d >= 0; d--) {
    if (t < 256) hist[t] = 0;
    __syncthreads();
    unsigned long long pref = sPrefix;
    int shift = d * 8;
    for (int j = t; j < KA; j += 1024) {
      unsigned long long key = make_key(sc[j], j);
      bool inpref = (d == 7) || (((key ^ pref) >> (shift + 8)) == 0ull);
      if (inpref) atomicAdd(&hist[(unsigned)((key >> shift) & 255ull)], 1u);
    }
    __syncthreads();
    if (t == 0) {
      int r = sR, cum = 0, b = 0;
      for (; b < 255; b++) {
        int hb = (int)hist[b];
        if (cum + hb > r) break;
        cum += hb;
      }
      sR = r - cum;
      sPrefix = pref | ((unsigned long long)b << shift);
    }
    __syncthreads();
  }
  unsigned long long T = sPrefix;

  for (int i = t; i < 4096; i += 1024) keys[i] = ~0ull;
  __syncthreads();
  for (int j = t; j < KA; j += 1024) {
    unsigned long long key = make_key(sc[j], j);
    if (key <= T) { int pos = atomicAdd(&sCnt, 1); if (pos < 4096) keys[pos] = key; }
  }
  __syncthreads();

  for (int k = 2; k <= 4096; k <<= 1) {
    for (int s = k >> 1; s > 0; s >>= 1) {
      for (int i = t; i < 4096; i += 1024) {
        int l = i ^ s;
        if (l > i) {
          unsigned long long A = keys[i], B = keys[l];
          bool asc = ((i & k) == 0);
          if ((A > B) == asc) { keys[i] = B; keys[l] = A; }
        }
      }
      __syncthreads();
    }
  }

  float rbx1[3], rby1[3], rbx2[3], rby2[3], rar[3], rss[3];
#pragma unroll
  for (int k = 0; k < 3; k++) {
    int i = t + k * 1024;
    if (i < NPRE) {
      int j = (int)(keys[i] & 0xffffffffull);
      float4 bb = *(const float4*)(g_roi + ((size_t)n * KA + j) * 4);
      float area = (bb.z - bb.x) * (bb.w - bb.y);
      bx1[i] = bb.x; by1[i] = bb.y; bx2[i] = bb.z; by2[i] = bb.w; ar[i] = area;
      rbx1[k] = bb.x; rby1[k] = bb.y; rbx2[k] = bb.z; rby2[k] = bb.w;
      rar[k] = area; rss[k] = sc[j];
    }
  }
  __syncthreads();

  int lane = t & 31, warp = t >> 5;
  const unsigned monoThr = f2mono(-5e8f);

  {
    unsigned long long best = 0ull;
#pragma unroll
    for (int k = 0; k < 3; k++) {
      int i = t + k * 1024;
      if (i < NPRE) {
        unsigned long long cand =
            (((unsigned long long)f2mono(rss[k])) << 32) | (unsigned)(~(unsigned)i);
        if (cand > best) best = cand;
      }
    }
#pragma unroll
    for (int off = 16; off > 0; off >>= 1) {
      unsigned long long o2 = __shfl_down_sync(0xffffffffu, best, off);
      if (o2 > best) best = o2;
    }
    if (lane == 0) red[warp] = best;
    __syncthreads();
    if (t < 32) {
      unsigned long long v = red[t];
#pragma unroll
      for (int off = 16; off > 0; off >>= 1) {
        unsigned long long o2 = __shfl_down_sync(0xffffffffu, v, off);
        if (o2 > v) v = o2;
      }
      if (t == 0) sBest = v;
    }
    __syncthreads();
  }

  for (int it = 0; it < NPOST; it++) {
    unsigned long long bb = sBest;
    int ij = (int)(~(unsigned)(bb & 0xffffffffull));
    bool valid = ((unsigned)(bb >> 32)) > monoThr;
    if (t == 0) keep_s[it] = valid ? ij : -1;
    float jx1 = bx1[ij], jy1 = by1[ij], jx2 = bx2[ij], jy2 = by2[ij], ja = ar[ij];

    unsigned long long best = 0ull;
#pragma unroll
    for (int k = 0; k < 3; k++) {
      int i = t + k * 1024;
      if (i < NPRE) {
        float xx1 = fmaxf(rbx1[k], jx1);
        float yy1 = fmaxf(rby1[k], jy1);
        float xx2 = fminf(rbx2[k], jx2);
        float yy2 = fminf(rby2[k], jy2);
        float inter = fmaxf(xx2 - xx1, 0.f) * fmaxf(yy2 - yy1, 0.f);
        float iou = inter / (rar[k] + ja - inter + 1e-9f);
        if (iou > 0.7f || i == ij || !valid) rss[k] = -1e9f;
        unsigned long long cand =
            (((unsigned long long)f2mono(rss[k])) << 32) | (unsigned)(~(unsigned)i);
        if (cand > best) best = cand;
      }
    }
#pragma unroll
    for (int off = 16; off > 0; off >>= 1) {
      unsigned long long o2 = __shfl_down_sync(0xffffffffu, best, off);
      if (o2 > best) best = o2;
    }
    if (lane == 0) red[warp] = best;
    __syncthreads();
    if (t < 32) {
      unsigned long long v = red[t];
#pragma unroll
      for (int off = 16; off > 0; off >>= 1) {
        unsigned long long o2 = __shfl_down_sync(0xffffffffu, v, off);
        if (o2 > v) v = o2;
      }
      if (t == 0) sBest = v;
    }
    __syncthreads();
  }

  for (int i = t; i < NPOST; i += 1024) {
    int kk = keep_s[i];
    float ox1 = 0.f, oy1 = 0.f, ox2 = 0.f, oy2 = 0.f, ridx = -1.f;
    if (kk >= 0) { ox1 = bx1[kk]; oy1 = by1[kk]; ox2 = bx2[kk]; oy2 = by2[kk]; ridx = (float)n; }
    int o = n * NPOST + i;
    out[OFF_ROIS + o * 4 + 0] = ox1;
    out[OFF_ROIS + o * 4 + 1] = oy1;
    out[OFF_ROIS + o * 4 + 2] = ox2;
    out[OFF_ROIS + o * 4 + 3] = oy2;
    out[OFF_RIDX + o] = ridx;
  }
}

// ---------------- launch ----------------
extern "C" void kernel_launch(void* const* d_in, const int* in_sizes, int n_in,
                              void* d_out, int out_size) {
  const float* x  = (const float*)d_in[0];
  const float* W1 = (const float*)d_in[1];
  const float* b1 = (const float*)d_in[2];
  const float* Ws = (const float*)d_in[3];
  const float* bs = (const float*)d_in[4];
  const float* Wl = (const float*)d_in[5];
  const float* bl = (const float*)d_in[6];
  const int* ih = (n_in > 7) ? (const int*)d_in[7] : nullptr;
  const int* iw = (n_in > 8) ? (const int*)d_in[8] : nullptr;
  float* out = (float*)d_out;

  cudaFuncSetAttribute(nms_kernel, cudaFuncAttributeMaxDynamicSharedMemorySize, NMS_SMEM);

  int tail_blocks = (512 * 64 + KA + 255) / 256;
  prep_w<<<256 + tail_blocks, 256>>>(W1, Wl, Ws, out);
  conv3x3<<<dim3(256, 4), 256>>>(x, b1);
  conv1x1<<<512, 256>>>(bl, bs, ih, iw, out);
  nms_kernel<<<NIMG, 1024, NMS_SMEM>>>(out);
}